// round 13
// baseline (speedup 1.0000x reference)
#include <cuda_runtime.h>
#include <cstdint>

// ---------------- problem constants (from reference) ----------------
#define FH    32
#define FW    88
#define NCAM  6
#define ND    118
#define NC    80
#define NXX   360
#define NYY   360
#define NPTS  (NCAM*ND*FH*FW)      // 1,993,728
#define NCELL (NXX*NYY)            // 129,600
#define GRID_ELEMS (NCELL*NC)      // 10,368,000 floats
#define PT_PER_CAM (ND*FH*FW)
#define PT_PER_D   (FH*FW)
#define NBLK1 507                  // ceil(NCELL/256)

// ---------------- device scratch (static: no allocation) ----------------
__device__ float g_scratch[GRID_ELEMS];
__device__ int   g_lin[NPTS];
__device__ int   g_cnt[NCELL];
__device__ int   g_off[NCELL];
__device__ int   g_cur[NCELL];
__device__ int   g_blk[512];
__device__ int   g_idx[NPTS];
// per-camera: [0:9) invPostRot [9:12) post_trans [12:21) G = E*rots*invK [21:24) E*trans+ET
__device__ float g_cam[NCAM][24];

// ---------------- exact-fp32 helpers (no FMA contraction) ----------------
__device__ __forceinline__ float dot3(const float* m, float a, float b, float c) {
    return __fadd_rn(__fadd_rn(__fmul_rn(m[0], a), __fmul_rn(m[1], b)),
                     __fmul_rn(m[2], c));
}

__device__ __forceinline__ void inv3(const float m[9], float out[9]) {
    float a=m[0],b=m[1],c=m[2],d=m[3],e=m[4],f=m[5],g=m[6],h=m[7],i=m[8];
    float A =  (e*i - f*h);
    float B = -(d*i - f*g);
    float C =  (d*h - e*g);
    float det = a*A + b*B + c*C;
    float id = 1.0f / det;
    out[0] =  A*id;            out[1] = -(b*i - c*h)*id;  out[2] =  (b*f - c*e)*id;
    out[3] =  B*id;            out[4] =  (a*i - c*g)*id;  out[5] = -(a*f - c*d)*id;
    out[6] =  C*id;            out[7] = -(a*h - b*g)*id;  out[8] =  (a*e - b*d)*id;
}

__device__ __forceinline__ void mm3(const float A[9], const float B[9], float C[9]) {
    #pragma unroll
    for (int i = 0; i < 3; i++)
        #pragma unroll
        for (int j = 0; j < 3; j++)
            C[i*3+j] = __fadd_rn(__fadd_rn(__fmul_rn(A[i*3+0], B[0*3+j]),
                                           __fmul_rn(A[i*3+1], B[1*3+j])),
                                 __fmul_rn(A[i*3+2], B[2*3+j]));
}

// ---------------- kernel 0: zero the per-voxel counters ----------------
__global__ void zero_cnt_kernel() {
    int i = blockIdx.x * blockDim.x + threadIdx.x;
    if (i < NCELL) g_cnt[i] = 0;
}

// ---------------- kernel 1: per-camera transform setup (exact fp32) ----------------
__global__ void setup_kernel(const float* __restrict__ c2l,
                             const float* __restrict__ intr,
                             const float* __restrict__ ida,
                             const float* __restrict__ bda) {
    int n = threadIdx.x;
    if (n >= NCAM) return;

    const float* M = c2l + n*16;
    float rots[9]  = {M[0],M[1],M[2],  M[4],M[5],M[6],  M[8],M[9],M[10]};
    float trans[3] = {M[3], M[7], M[11]};

    const float* Ki = intr + n*16;
    float K[9] = {Ki[0],Ki[1],Ki[2], Ki[4],Ki[5],Ki[6], Ki[8],Ki[9],Ki[10]};

    const float* Ai = ida + n*16;
    float PR[9] = {Ai[0],Ai[1],Ai[2], Ai[4],Ai[5],Ai[6], Ai[8],Ai[9],Ai[10]};
    float PT[3] = {Ai[3], Ai[7], Ai[11]};

    float E[9]  = {bda[0],bda[1],bda[2], bda[4],bda[5],bda[6], bda[8],bda[9],bda[10]};
    float ET[3] = {bda[3], bda[7], bda[11]};

    float invK[9], invPR[9], cmb[9], G[9];
    inv3(K, invK);
    inv3(PR, invPR);
    mm3(rots, invK, cmb);   // combine = rots @ inv(intrins); exact-identity rows stay exact
    mm3(E, cmb, G);         // E is identity in this data -> G == cmb bit-exactly

    float o[3];
    #pragma unroll
    for (int i = 0; i < 3; i++)
        o[i] = __fadd_rn(dot3(E + i*3, trans[0], trans[1], trans[2]), ET[i]);

    float* cp = g_cam[n];
    #pragma unroll
    for (int i = 0; i < 9; i++) cp[i]      = invPR[i];
    #pragma unroll
    for (int i = 0; i < 3; i++) cp[9 + i]  = PT[i];
    #pragma unroll
    for (int i = 0; i < 9; i++) cp[12 + i] = G[i];
    #pragma unroll
    for (int i = 0; i < 3; i++) cp[21 + i] = o[i];
}

// ---------------- kernel 2: geometry -> voxel index + histogram ----------------
// depth_kept: jnp bool materialized as int32 (confirmed by the 25%-kept signature)
__global__ void geom_kernel(const int* __restrict__ depth_kept) {
    int p = blockIdx.x * blockDim.x + threadIdx.x;
    if (p >= NPTS) return;

    int n  = p / PT_PER_CAM;
    int r  = p - n * PT_PER_CAM;
    int d  = r / PT_PER_D;
    int r2 = r - d * PT_PER_D;
    int h  = r2 / FW;
    int w  = r2 - h * FW;

    const float* cp = g_cam[n];

    // frustum (linspace: iota*step; arange: start + iota*step)
    const float STEPX = 703.0f / 87.0f;   // compile-time IEEE-RN fold
    const float STEPY = 255.0f / 31.0f;
    float fx = __fmul_rn((float)w, STEPX);
    float fy = __fmul_rn((float)h, STEPY);
    float fd = __fadd_rn(1.0f, __fmul_rn(0.5f, (float)d));

    // pts = frustum - post_trans
    float p0 = __fadd_rn(fx, -cp[9]);
    float p1 = __fadd_rn(fy, -cp[10]);
    float p2 = __fadd_rn(fd, -cp[11]);

    // einsum1: inv(post_rots) @ pts (identity in this data -> exact passthrough)
    float q0 = dot3(cp + 0, p0, p1, p2);
    float q1 = dot3(cp + 3, p0, p1, p2);
    float q2 = dot3(cp + 6, p0, p1, p2);

    // (x*z, y*z, z)
    float r0 = __fmul_rn(q0, q2);
    float r1 = __fmul_rn(q1, q2);

    // combine einsum + trans (E folded; exact for identity E)
    float px = __fadd_rn(dot3(cp + 12, r0, r1, q2), cp[21]);
    float py = __fadd_rn(dot3(cp + 15, r0, r1, q2), cp[22]);
    float pz = __fadd_rn(dot3(cp + 18, r0, r1, q2), cp[23]);

    // voxelize EXACTLY as XLA lowers it: division by the constant vector DX is
    // rewritten to multiplication by the fp32-RN reciprocal. This decides the
    // exact-boundary slabs (cams 0/3: px+54 = 55.5+0.5k on voxel edges) the
    // same way the reference does — IEEE div.rn lands a 3.5% slab subset one
    // voxel lower (the j/2^e > 1.494 binade band), which was the entire 0.281.
    const float INV_DXY = 1.0f / 0.3f;    // RN(1/0.3f), compile-time fold
    const float INV_DZ  = 1.0f / 20.0f;
    int cx = (int)floorf(__fmul_rn(__fadd_rn(px, 54.0f), INV_DXY));
    int cy = (int)floorf(__fmul_rn(__fadd_rn(py, 54.0f), INV_DXY));
    int cz = (int)floorf(__fmul_rn(__fadd_rn(pz, 10.0f), INV_DZ));

    bool ok = (cx >= 0) & (cx < NXX) & (cy >= 0) & (cy < NYY) &
              (cz >= 0) & (cz < 1)   & (depth_kept[p] != 0);

    int lin = ok ? (cx * NYY + cy) : -1;
    g_lin[p] = lin;
    if (ok) atomicAdd(&g_cnt[lin], 1);
}

// ---------------- kernels 3a/3b/3c: exclusive prefix scan of g_cnt ----------------
__global__ void scan_a_kernel() {
    __shared__ int s[256];
    int gid = blockIdx.x * 256 + threadIdx.x;
    int v = (gid < NCELL) ? g_cnt[gid] : 0;
    s[threadIdx.x] = v;
    __syncthreads();
    for (int dd = 1; dd < 256; dd <<= 1) {
        int t = (threadIdx.x >= dd) ? s[threadIdx.x - dd] : 0;
        __syncthreads();
        s[threadIdx.x] += t;
        __syncthreads();
    }
    if (gid < NCELL) g_off[gid] = s[threadIdx.x] - v;
    if (threadIdx.x == 255) g_blk[blockIdx.x] = s[255];
}

__global__ void scan_b_kernel() {
    __shared__ int s[512];
    int v = (threadIdx.x < NBLK1) ? g_blk[threadIdx.x] : 0;
    s[threadIdx.x] = v;
    __syncthreads();
    for (int dd = 1; dd < 512; dd <<= 1) {
        int t = (threadIdx.x >= dd) ? s[threadIdx.x - dd] : 0;
        __syncthreads();
        s[threadIdx.x] += t;
        __syncthreads();
    }
    if (threadIdx.x < NBLK1) g_blk[threadIdx.x] = s[threadIdx.x] - v;
}

__global__ void scan_c_kernel() {
    int gid = blockIdx.x * 256 + threadIdx.x;
    if (gid < NCELL) {
        int o = g_off[gid] + g_blk[blockIdx.x];
        g_off[gid] = o;
        g_cur[gid] = o;
    }
}

// ---------------- kernel 4: fill per-voxel point lists ----------------
__global__ void fill_kernel() {
    int p = blockIdx.x * blockDim.x + threadIdx.x;
    if (p >= NPTS) return;
    int lin = g_lin[p];
    if (lin < 0) return;
    int pos = atomicAdd(&g_cur[lin], 1);
    g_idx[pos] = p;
}

// ---------------- kernel 5: gather-sum, one warp per voxel, no float atomics ----------------
__global__ void gather_kernel(const float* __restrict__ x) {
    int warp = (blockIdx.x * blockDim.x + threadIdx.x) >> 5;
    int lane = threadIdx.x & 31;
    if (warp >= NCELL) return;

    int beg = g_off[warp];
    int end = g_cur[warp];

    float a0 = 0.f, a1 = 0.f, a2 = 0.f;
    int c0 = lane, c1 = lane + 32, c2 = lane + 64;

    int i = beg;
    for (; i + 4 <= end; i += 4) {
        #pragma unroll
        for (int u = 0; u < 4; u++) {
            const float* row = x + (size_t)__ldg(&g_idx[i + u]) * NC;
            a0 += __ldg(&row[c0]);
            a1 += __ldg(&row[c1]);
            if (lane < 16) a2 += __ldg(&row[c2]);
        }
    }
    for (; i < end; i++) {
        const float* row = x + (size_t)__ldg(&g_idx[i]) * NC;
        a0 += __ldg(&row[c0]);
        a1 += __ldg(&row[c1]);
        if (lane < 16) a2 += __ldg(&row[c2]);
    }

    float* dst = g_scratch + (size_t)warp * NC;
    dst[c0] = a0;
    dst[c1] = a1;
    if (lane < 16) dst[c2] = a2;
}

// ---------------- kernel 6: (cell, C) -> (C, cell) transpose into output ----------------
__global__ void transpose_kernel(float* __restrict__ out) {
    __shared__ float tile[32][NC + 1];
    int lin0 = blockIdx.x * 32;

    for (int i = threadIdx.x; i < 32 * NC; i += blockDim.x) {
        int l = i / NC;
        int c = i - l * NC;
        tile[l][c] = g_scratch[(size_t)(lin0 + l) * NC + c];
    }
    __syncthreads();
    for (int i = threadIdx.x; i < 32 * NC; i += blockDim.x) {
        int c = i / 32;
        int l = i - c * 32;
        out[(size_t)c * NCELL + lin0 + l] = tile[l][c];
    }
}

// ---------------- launch ----------------
extern "C" void kernel_launch(void* const* d_in, const int* in_sizes, int n_in,
                              void* d_out, int out_size) {
    const float* x    = (const float*)d_in[0];
    const int*   kept = (const int*)d_in[1];     // bool materialized as int32
    const float* c2l  = (const float*)d_in[2];
    const float* intr = (const float*)d_in[3];
    const float* ida  = (const float*)d_in[4];
    const float* bda  = (const float*)d_in[5];
    float* out = (float*)d_out;

    zero_cnt_kernel<<<NBLK1, 256>>>();
    setup_kernel<<<1, 32>>>(c2l, intr, ida, bda);
    geom_kernel<<<(NPTS + 255) / 256, 256>>>(kept);
    scan_a_kernel<<<NBLK1, 256>>>();
    scan_b_kernel<<<1, 512>>>();
    scan_c_kernel<<<NBLK1, 256>>>();
    fill_kernel<<<(NPTS + 255) / 256, 256>>>();
    gather_kernel<<<NCELL / 8, 256>>>(x);
    transpose_kernel<<<NCELL / 32, 256>>>(out);
}